// round 5
// baseline (speedup 1.0000x reference)
#include <cuda_runtime.h>

#define NQ   512
#define NK   1024
#define DIMC 256
#define NH   8
#define HD   32
#define RPE  512
#define NSEG (RPE + 1)

// ---------------- scratch (static __device__ — allocation-free) ----------------
static __device__ float          g_tsort[RPE];
static __device__ float          g_A[NH * NSEG];
static __device__ float          g_C[NH * NSEG];
static __device__ unsigned short g_seg[NQ * NK];
static __device__ float          g_q[NQ * DIMC];
static __device__ float          g_k[NK * DIMC];
static __device__ float          g_v[NK * DIMC];
static __device__ float          g_x[NQ * DIMC];

// =============================================================================
// Kernel 1: piecewise-linear CPB bias tables (rank-sort, 2 syncs).
// =============================================================================
__global__ void pwl_build(const float* __restrict__ W1, const float* __restrict__ b1,
                          const float* __restrict__ W2) {
    __shared__ float key[RPE];
    __shared__ float skey[RPE];
    __shared__ int   sidx[RPE];
    __shared__ float sW1[RPE], sb1[RPE];
    __shared__ float sW2[RPE * NH];

    const int tid = threadIdx.x;
    float w = W1[tid], b = b1[tid];
    float t;
    if (w != 0.0f) t = -b / w;
    else t = (b > 0.0f) ? -__int_as_float(0x7f800000) : __int_as_float(0x7f800000);
    key[tid] = t;
    sW1[tid] = w;
    sb1[tid] = b;
#pragma unroll
    for (int h = 0; h < NH; h++) sW2[tid * NH + h] = W2[tid * NH + h];
    __syncthreads();

    int rank = 0;
    float ki = t;
#pragma unroll 4
    for (int j4 = 0; j4 < RPE / 4; j4++) {
        float4 kj = *(const float4*)&key[j4 * 4];
        int j = j4 * 4;
        rank += (kj.x < ki) || (kj.x == ki && (j + 0) < tid);
        rank += (kj.y < ki) || (kj.y == ki && (j + 1) < tid);
        rank += (kj.z < ki) || (kj.z == ki && (j + 2) < tid);
        rank += (kj.w < ki) || (kj.w == ki && (j + 3) < tid);
    }
    skey[rank] = ki;
    sidx[rank] = tid;
    __syncthreads();
    g_tsort[tid] = skey[tid];

    const int warp = tid >> 5, lane = tid & 31;
    if (warp < NH) {
        const int h = warp;
        float eA[16], eC[16];
        float leA = 0.f, leC = 0.f, mA = 0.f, mC = 0.f;
#pragma unroll
        for (int pp = 0; pp < 16; pp++) {
            int p = lane * 16 + pp;
            int r = sidx[p];
            float w1 = sW1[r], bb = sb1[r], w2 = sW2[r * NH + h];
            float ca, cc; bool plus;
            if (w1 > 0.f)      { plus = true;  ca = w1 * w2; cc = bb * w2; }
            else if (w1 < 0.f) { plus = false; ca = w1 * w2; cc = bb * w2; }
            else               { plus = true;  ca = 0.f;     cc = (bb > 0.f) ? bb * w2 : 0.f; }
            float ea = plus ? ca : -ca;
            float ec = plus ? cc : -cc;
            eA[pp] = ea; eC[pp] = ec;
            leA += ea; leC += ec;
            if (!plus) { mA += ca; mC += cc; }
        }
        float inA = leA, inC = leC;
#pragma unroll
        for (int o = 1; o < 32; o <<= 1) {
            float ta = __shfl_up_sync(0xffffffffu, inA, o);
            float tc = __shfl_up_sync(0xffffffffu, inC, o);
            if (lane >= o) { inA += ta; inC += tc; }
        }
        float exA = inA - leA, exC = inC - leC;
#pragma unroll
        for (int o = 16; o > 0; o >>= 1) {
            mA += __shfl_xor_sync(0xffffffffu, mA, o);
            mC += __shfl_xor_sync(0xffffffffu, mC, o);
        }
        if (lane == 0) { g_A[h * NSEG] = mA; g_C[h * NSEG] = mC; }
        float runA = exA, runC = exC;
#pragma unroll
        for (int pp = 0; pp < 16; pp++) {
            runA += eA[pp]; runC += eC[pp];
            int s = lane * 16 + pp + 1;
            g_A[h * NSEG + s] = mA + runA;
            g_C[h * NSEG + s] = mC + runC;
        }
    }
}

// =============================================================================
// Kernel 2: segment index per (q,k) — 4 elements per thread.
// =============================================================================
__global__ void seg_kernel(const float* __restrict__ am) {
    __shared__ float ts[RPE];
    int t = threadIdx.x;
    ts[t] = g_tsort[t];
    ts[t + 256] = g_tsort[t + 256];
    __syncthreads();
    int i0 = (blockIdx.x * 256 + t) * 4;
    float4 m4 = *(const float4*)&am[i0];
    float mv[4] = {m4.x, m4.y, m4.z, m4.w};
    unsigned short sg[4];
#pragma unroll
    for (int e = 0; e < 4; e++) {
        float m = mv[e];
        int lo = 0, hi = RPE;
        while (lo < hi) {
            int mid = (lo + hi) >> 1;
            if (ts[mid] <= m) lo = mid + 1; else hi = mid;
        }
        sg[e] = (unsigned short)lo;
    }
    *(ushort4*)&g_seg[i0] = make_ushort4(sg[0], sg[1], sg[2], sg[3]);
}

// =============================================================================
// Shared GEMM body: 64x64 tile / block, 128 threads, 4x8 per thread, BK=16.
// =============================================================================
__device__ __forceinline__ void gemm_body(const float* __restrict__ A, const float* __restrict__ W,
                                          const float* __restrict__ bias, float* __restrict__ C,
                                          int M, float scale) {
    __shared__ float As[16][68];
    __shared__ float Ws[16][72];
    int bm = blockIdx.y * 64;
    if (bm >= M) return;
    int bn = blockIdx.x * 64;
    int t = threadIdx.x;
    int ra = t >> 1, ka = (t & 1) * 8;
    int kw = t >> 3, nw = (t & 7) * 8;
    int ty = t >> 3, tx = t & 7;
    float acc[4][8] = {};
    for (int k0 = 0; k0 < DIMC; k0 += 16) {
        float4 a0 = *(const float4*)&A[(bm + ra) * DIMC + k0 + ka];
        float4 a1 = *(const float4*)&A[(bm + ra) * DIMC + k0 + ka + 4];
        float4 w0 = *(const float4*)&W[(k0 + kw) * DIMC + bn + nw];
        float4 w1 = *(const float4*)&W[(k0 + kw) * DIMC + bn + nw + 4];
        As[ka + 0][ra] = a0.x; As[ka + 1][ra] = a0.y; As[ka + 2][ra] = a0.z; As[ka + 3][ra] = a0.w;
        As[ka + 4][ra] = a1.x; As[ka + 5][ra] = a1.y; As[ka + 6][ra] = a1.z; As[ka + 7][ra] = a1.w;
        *(float4*)&Ws[kw][nw]     = w0;
        *(float4*)&Ws[kw][nw + 4] = w1;
        __syncthreads();
#pragma unroll
        for (int kk = 0; kk < 16; kk++) {
            float4 a4 = *(const float4*)&As[kk][ty * 4];
            float4 b0 = *(const float4*)&Ws[kk][tx * 8];
            float4 b1 = *(const float4*)&Ws[kk][tx * 8 + 4];
            float aa[4] = {a4.x, a4.y, a4.z, a4.w};
            float bb[8] = {b0.x, b0.y, b0.z, b0.w, b1.x, b1.y, b1.z, b1.w};
#pragma unroll
            for (int i = 0; i < 4; i++)
#pragma unroll
                for (int j = 0; j < 8; j++)
                    acc[i][j] += aa[i] * bb[j];
        }
        __syncthreads();
    }
    float4 bsa = *(const float4*)&bias[bn + tx * 8];
    float4 bsb = *(const float4*)&bias[bn + tx * 8 + 4];
    float bs[8] = {bsa.x, bsa.y, bsa.z, bsa.w, bsb.x, bsb.y, bsb.z, bsb.w};
#pragma unroll
    for (int i = 0; i < 4; i++) {
        int row = bm + ty * 4 + i;
        float4 o0, o1;
        o0.x = (acc[i][0] + bs[0]) * scale; o0.y = (acc[i][1] + bs[1]) * scale;
        o0.z = (acc[i][2] + bs[2]) * scale; o0.w = (acc[i][3] + bs[3]) * scale;
        o1.x = (acc[i][4] + bs[4]) * scale; o1.y = (acc[i][5] + bs[5]) * scale;
        o1.z = (acc[i][6] + bs[6]) * scale; o1.w = (acc[i][7] + bs[7]) * scale;
        *(float4*)&C[row * DIMC + bn + tx * 8]     = o0;
        *(float4*)&C[row * DIMC + bn + tx * 8 + 4] = o1;
    }
}

__global__ void __launch_bounds__(128) gemm_qkv(
        const float* __restrict__ q_in, const float* __restrict__ k_in,
        const float* __restrict__ v_in,
        const float* __restrict__ Wq, const float* __restrict__ bq_,
        const float* __restrict__ Wk, const float* __restrict__ bk_,
        const float* __restrict__ Wv, const float* __restrict__ bv_) {
    const float *A, *W, *B; float *Cp; int M; float sc;
    if (blockIdx.z == 0)      { A = q_in; W = Wq; B = bq_; Cp = g_q; M = NQ; sc = 0.17677669529663687f; }
    else if (blockIdx.z == 1) { A = k_in; W = Wk; B = bk_; Cp = g_k; M = NK; sc = 1.0f; }
    else                      { A = v_in; W = Wv; B = bv_; Cp = g_v; M = NK; sc = 1.0f; }
    gemm_body(A, W, B, Cp, M, sc);
}

__global__ void __launch_bounds__(128) gemm_final(
        const float* __restrict__ Wp, const float* __restrict__ bp_,
        float* __restrict__ out) {
    gemm_body(g_x, Wp, bp_, out, NQ, 1.0f);
}

// =============================================================================
// Kernel 4: FUSED attention — 512 threads (16 warps), 1 block/SM, ~197KB smem.
// ST[k 1024][q 32] stride 36 (transposed scores).
// Phase A: QK^T + PWL-bias + pad, chunks of 256 k (single K^T buf + prefetch)
// Phase B: softmax columns (16 warps x 64 k-rows, q = lane)
// Phase C: O = PV (4q x 8d x 16 split-k, V dbl-buffered, shfl reduce)
// =============================================================================
#define TQ      32
#define STSTR   36
#define KTSTR   260
#define VSTR    36
#define VBUF    (128 * VSTR)              // 4608 floats per buffer
#define OFF_ST  0
#define OFF_KV  (NK * STSTR)              // 36864  (union: Kt 8320 / V dbl 9216)
#define OFF_Q   (OFF_KV + 2 * VBUF)       // 46080
#define OFF_AC  (OFF_Q + 32 * 36)         // 47232
#define OFF_PAD (OFF_AC + 2 * NSEG + 2)   // 48260 (16B aligned)
#define OFF_PM  (OFF_PAD + NK)            // 49284
#define OFF_PS  (OFF_PM + 512)
#define OFF_LI  (OFF_PS + 512)
#define SMEM_FLOATS (OFF_LI + 32)
#define SMEM_BYTES  (SMEM_FLOATS * 4)

__global__ void __launch_bounds__(512, 1) fused_attn(const float* __restrict__ am,
                                                     const float* __restrict__ pad) {
    extern __shared__ float sm[];
    float*  ST   = sm + OFF_ST;
    float*  KV   = sm + OFF_KV;
    float*  Qs   = sm + OFF_Q;      // [d][q], stride 36
    float2* AC   = (float2*)(sm + OFF_AC);
    float*  padp = sm + OFF_PAD;
    float*  pm   = sm + OFF_PM;
    float*  ps   = sm + OFF_PS;
    float*  linv = sm + OFF_LI;

    const int h    = blockIdx.y;
    const int bq   = blockIdx.x * TQ;
    const int t    = threadIdx.x;
    const int lane = t & 31, warp = t >> 5;

    // ---- prologue ----
    if (t < 256) {
        int qr = t >> 3, d4 = (t & 7) * 4;
        float4 v = *(const float4*)&g_q[(bq + qr) * DIMC + h * HD + d4];
        Qs[(d4 + 0) * 36 + qr] = v.x; Qs[(d4 + 1) * 36 + qr] = v.y;
        Qs[(d4 + 2) * 36 + qr] = v.z; Qs[(d4 + 3) * 36 + qr] = v.w;
        float4 p4 = *(const float4*)&pad[t * 4];
        float4 o; o.x = p4.x * -100.f; o.y = p4.y * -100.f; o.z = p4.z * -100.f; o.w = p4.w * -100.f;
        *(float4*)&padp[t * 4] = o;
    }
    for (int i = t; i < NSEG; i += 512)
        AC[i] = make_float2(g_A[h * NSEG + i], g_C[h * NSEG + i]);

    // ---- Phase A: 4 chunks of 256 k; thread tile 4k x 4q ----
    const int kr   = t >> 1;              // 0..255 (k row within chunk)
    const int half = (t & 1) * 16;        // d half
    const int tk4  = t >> 3;              // 0..63  (compute: 4 k)
    const int tq4  = t & 7;               // 0..7   (compute: 4 q)
    float* Kt = KV;                       // [32 d][260]

    float4 kv0, kv1, kv2, kv3;
    {
        const float* p = &g_k[kr * DIMC + h * HD + half];
        kv0 = *(const float4*)p;       kv1 = *(const float4*)(p + 4);
        kv2 = *(const float4*)(p + 8); kv3 = *(const float4*)(p + 12);
    }
    for (int c = 0; c < 4; c++) {
        __syncthreads();                  // Kt free (prev compute done) + prologue
        {
            float* B = Kt + half * KTSTR + kr;
            B[0 * KTSTR] = kv0.x; B[1 * KTSTR] = kv0.y; B[2 * KTSTR] = kv0.z; B[3 * KTSTR] = kv0.w;
            B[4 * KTSTR] = kv1.x; B[5 * KTSTR] = kv1.y; B[6 * KTSTR] = kv1.z; B[7 * KTSTR] = kv1.w;
            B[8 * KTSTR] = kv2.x; B[9 * KTSTR] = kv2.y; B[10* KTSTR] = kv2.z; B[11* KTSTR] = kv2.w;
            B[12* KTSTR] = kv3.x; B[13* KTSTR] = kv3.y; B[14* KTSTR] = kv3.z; B[15* KTSTR] = kv3.w;
        }
        __syncthreads();
        if (c < 3) {                      // prefetch next chunk under compute
            const float* p = &g_k[((c + 1) * 256 + kr) * DIMC + h * HD + half];
            kv0 = *(const float4*)p;       kv1 = *(const float4*)(p + 4);
            kv2 = *(const float4*)(p + 8); kv3 = *(const float4*)(p + 12);
        }
        float acc[4][4] = {};             // [ki][qj]
#pragma unroll
        for (int d = 0; d < HD; d++) {
            float4 kb = *(const float4*)&Kt[d * KTSTR + tk4 * 4];
            float4 qa = *(const float4*)&Qs[d * 36 + tq4 * 4];
            float kvv[4] = {kb.x, kb.y, kb.z, kb.w};
            float qv[4]  = {qa.x, qa.y, qa.z, qa.w};
#pragma unroll
            for (int i = 0; i < 4; i++)
#pragma unroll
                for (int j = 0; j < 4; j++)
                    acc[i][j] += kvv[i] * qv[j];
        }
        const int kg0 = c * 256 + tk4 * 4;
#pragma unroll
        for (int j = 0; j < 4; j++) {
            int qg = bq + tq4 * 4 + j;
            float4  m4 = *(const float4*)&am[qg * NK + kg0];
            ushort4 s4 = *(const ushort4*)&g_seg[qg * NK + kg0];
            float2 c0 = AC[s4.x], c1 = AC[s4.y], c2 = AC[s4.z], c3 = AC[s4.w];
            acc[0][j] += fmaf(c0.x, m4.x, c0.y);
            acc[1][j] += fmaf(c1.x, m4.y, c1.y);
            acc[2][j] += fmaf(c2.x, m4.z, c2.y);
            acc[3][j] += fmaf(c3.x, m4.w, c3.y);
        }
#pragma unroll
        for (int i = 0; i < 4; i++) {
            float pdv = padp[kg0 + i];
            float4 o;
            o.x = acc[i][0] + pdv; o.y = acc[i][1] + pdv;
            o.z = acc[i][2] + pdv; o.w = acc[i][3] + pdv;
            *(float4*)&ST[(kg0 + i) * STSTR + tq4 * 4] = o;
        }
    }
    __syncthreads();

    // ---- Phase B: softmax; warp w covers k in [w*64, w*64+64), q = lane ----
    {
        const int kb = warp * 64;
        float mx = -3.0e38f;
#pragma unroll 4
        for (int i = 0; i < 64; i++)
            mx = fmaxf(mx, ST[(kb + i) * STSTR + lane]);
        pm[warp * 32 + lane] = mx;
        __syncthreads();
        float gm = pm[lane];
#pragma unroll
        for (int j = 1; j < 16; j++) gm = fmaxf(gm, pm[j * 32 + lane]);
        float s = 0.f;
#pragma unroll 4
        for (int i = 0; i < 64; i++) {
            int idx = (kb + i) * STSTR + lane;
            float e = __expf(ST[idx] - gm);
            ST[idx] = e;
            s += e;
        }
        ps[warp * 32 + lane] = s;
        __syncthreads();
        if (warp == 0) {
            float tot = ps[lane];
#pragma unroll
            for (int j = 1; j < 16; j++) tot += ps[j * 32 + lane];
            linv[lane] = 1.0f / tot;
        }
    }
    __syncthreads();

    // ---- Phase C: O = P V; 8 chunks of 128 k, V dbl-buffered ----
    const int vkr = t >> 2;               // 0..127
    const int vdh = (t & 3) * 8;          // d offset
    float4 v0, v1;
    {
        const float* p = &g_v[vkr * DIMC + h * HD + vdh];
        v0 = *(const float4*)p; v1 = *(const float4*)(p + 4);
        float* B = KV + vkr * VSTR + vdh;
        *(float4*)B = v0; *(float4*)(B + 4) = v1;
    }
    __syncthreads();

    const int g    = t & 15;              // split-k group
    const int tile = t >> 4;              // 0..31
    const int q0   = (tile >> 2) * 4;
    const int d0   = (tile & 3) * 8;
    float acc[4][8] = {};
    for (int c = 0; c < 8; c++) {
        if (c < 7) {
            const float* p = &g_v[((c + 1) * 128 + vkr) * DIMC + h * HD + vdh];
            v0 = *(const float4*)p; v1 = *(const float4*)(p + 4);
        }
        const float* Vb = KV + (c & 1) * VBUF;
#pragma unroll
        for (int i = 0; i < 8; i++) {
            int kl = i * 16 + g;
            int kg = c * 128 + kl;
            float4 pA = *(const float4*)&ST[kg * STSTR + q0];
            float4 vA = *(const float4*)&Vb[kl * VSTR + d0];
            float4 vB = *(const float4*)&Vb[kl * VSTR + d0 + 4];
            float pq[4] = {pA.x, pA.y, pA.z, pA.w};
            float vd[8] = {vA.x, vA.y, vA.z, vA.w, vB.x, vB.y, vB.z, vB.w};
#pragma unroll
            for (int qi = 0; qi < 4; qi++)
#pragma unroll
                for (int di = 0; di < 8; di++)
                    acc[qi][di] += pq[qi] * vd[di];
        }
        if (c < 7) {
            float* B = KV + ((c + 1) & 1) * VBUF + vkr * VSTR + vdh;
            *(float4*)B = v0; *(float4*)(B + 4) = v1;
        }
        __syncthreads();
    }

    // split-k reduce over g (lane bits 0..3) via butterfly
#pragma unroll
    for (int o = 1; o < 16; o <<= 1)
#pragma unroll
        for (int qi = 0; qi < 4; qi++)
#pragma unroll
            for (int di = 0; di < 8; di++)
                acc[qi][di] += __shfl_xor_sync(0xffffffffu, acc[qi][di], o);

    if (g == 0) {
#pragma unroll
        for (int qi = 0; qi < 4; qi++) {
            int q = q0 + qi;
            float inv = linv[q];
            float4 oA, oB;
            oA.x = acc[qi][0] * inv; oA.y = acc[qi][1] * inv;
            oA.z = acc[qi][2] * inv; oA.w = acc[qi][3] * inv;
            oB.x = acc[qi][4] * inv; oB.y = acc[qi][5] * inv;
            oB.z = acc[qi][6] * inv; oB.w = acc[qi][7] * inv;
            float* op = &g_x[(bq + q) * DIMC + h * HD + d0];
            *(float4*)op = oA; *(float4*)(op + 4) = oB;
        }
    }
}

// =============================================================================
extern "C" void kernel_launch(void* const* d_in, const int* in_sizes, int n_in,
                              void* d_out, int out_size) {
    const float* query = (const float*)d_in[0];
    const float* kin   = (const float*)d_in[1];
    const float* vin   = (const float*)d_in[2];
    const float* pad   = (const float*)d_in[3];
    const float* am    = (const float*)d_in[4];
    const float* Wq    = (const float*)d_in[5];
    const float* bq    = (const float*)d_in[6];
    const float* Wk    = (const float*)d_in[7];
    const float* bk    = (const float*)d_in[8];
    const float* Wv    = (const float*)d_in[9];
    const float* bv    = (const float*)d_in[10];
    const float* Wp    = (const float*)d_in[11];
    const float* bp    = (const float*)d_in[12];
    const float* W1    = (const float*)d_in[13];
    const float* b1    = (const float*)d_in[14];
    const float* W2    = (const float*)d_in[15];
    float* out = (float*)d_out;

    cudaFuncSetAttribute(fused_attn, cudaFuncAttributeMaxDynamicSharedMemorySize, SMEM_BYTES);

    pwl_build<<<1, 512>>>(W1, b1, W2);
    seg_kernel<<<NQ * NK / 1024, 256>>>(am);
    gemm_qkv<<<dim3(4, 16, 3), 128>>>(query, kin, vin, Wq, bq, Wk, bk, Wv, bv);
    fused_attn<<<dim3(16, 8), 512, SMEM_BYTES>>>(am, pad);
    gemm_final<<<dim3(4, 8), 128>>>(Wp, bp, out);
}

// round 6
// speedup vs baseline: 1.0150x; 1.0150x over previous
#include <cuda_runtime.h>

#define NQ   512
#define NK   1024
#define DIMC 256
#define NH   8
#define HD   32
#define RPE  512
#define NSEG (RPE + 1)

typedef unsigned long long u64;

// ---- packed f32x2 helpers (Blackwell; ptxas never emits these from C++) ----
__device__ __forceinline__ u64 pk2(float lo, float hi) {
    u64 r; asm("mov.b64 %0, {%1, %2};" : "=l"(r) : "f"(lo), "f"(hi)); return r;
}
__device__ __forceinline__ void fma2(u64& d, u64 a, u64 b) {
    asm("fma.rn.f32x2 %0, %1, %2, %0;" : "+l"(d) : "l"(a), "l"(b));
}
__device__ __forceinline__ float2 up2(u64 d) {
    float2 f; asm("mov.b64 {%0, %1}, %2;" : "=f"(f.x), "=f"(f.y) : "l"(d)); return f;
}

// ---------------- scratch (static __device__ — allocation-free) ----------------
static __device__ float          g_tsort[RPE];
static __device__ float          g_A[NH * NSEG];
static __device__ float          g_C[NH * NSEG];
static __device__ unsigned short g_seg[NQ * NK];
static __device__ float          g_q[NQ * DIMC];
static __device__ float          g_k[NK * DIMC];
static __device__ float          g_v[NK * DIMC];
static __device__ float          g_x[NQ * DIMC];

// =============================================================================
// Kernel 1: piecewise-linear CPB bias tables (rank-sort, 2 syncs).
// =============================================================================
__global__ void pwl_build(const float* __restrict__ W1, const float* __restrict__ b1,
                          const float* __restrict__ W2) {
    __shared__ float key[RPE];
    __shared__ float skey[RPE];
    __shared__ int   sidx[RPE];
    __shared__ float sW1[RPE], sb1[RPE];
    __shared__ float sW2[RPE * NH];

    const int tid = threadIdx.x;
    float w = W1[tid], b = b1[tid];
    float t;
    if (w != 0.0f) t = -b / w;
    else t = (b > 0.0f) ? -__int_as_float(0x7f800000) : __int_as_float(0x7f800000);
    key[tid] = t;
    sW1[tid] = w;
    sb1[tid] = b;
#pragma unroll
    for (int h = 0; h < NH; h++) sW2[tid * NH + h] = W2[tid * NH + h];
    __syncthreads();

    int rank = 0;
    float ki = t;
#pragma unroll 4
    for (int j4 = 0; j4 < RPE / 4; j4++) {
        float4 kj = *(const float4*)&key[j4 * 4];
        int j = j4 * 4;
        rank += (kj.x < ki) || (kj.x == ki && (j + 0) < tid);
        rank += (kj.y < ki) || (kj.y == ki && (j + 1) < tid);
        rank += (kj.z < ki) || (kj.z == ki && (j + 2) < tid);
        rank += (kj.w < ki) || (kj.w == ki && (j + 3) < tid);
    }
    skey[rank] = ki;
    sidx[rank] = tid;
    __syncthreads();
    g_tsort[tid] = skey[tid];

    const int warp = tid >> 5, lane = tid & 31;
    if (warp < NH) {
        const int h = warp;
        float eA[16], eC[16];
        float leA = 0.f, leC = 0.f, mA = 0.f, mC = 0.f;
#pragma unroll
        for (int pp = 0; pp < 16; pp++) {
            int p = lane * 16 + pp;
            int r = sidx[p];
            float w1 = sW1[r], bb = sb1[r], w2 = sW2[r * NH + h];
            float ca, cc; bool plus;
            if (w1 > 0.f)      { plus = true;  ca = w1 * w2; cc = bb * w2; }
            else if (w1 < 0.f) { plus = false; ca = w1 * w2; cc = bb * w2; }
            else               { plus = true;  ca = 0.f;     cc = (bb > 0.f) ? bb * w2 : 0.f; }
            float ea = plus ? ca : -ca;
            float ec = plus ? cc : -cc;
            eA[pp] = ea; eC[pp] = ec;
            leA += ea; leC += ec;
            if (!plus) { mA += ca; mC += cc; }
        }
        float inA = leA, inC = leC;
#pragma unroll
        for (int o = 1; o < 32; o <<= 1) {
            float ta = __shfl_up_sync(0xffffffffu, inA, o);
            float tc = __shfl_up_sync(0xffffffffu, inC, o);
            if (lane >= o) { inA += ta; inC += tc; }
        }
        float exA = inA - leA, exC = inC - leC;
#pragma unroll
        for (int o = 16; o > 0; o >>= 1) {
            mA += __shfl_xor_sync(0xffffffffu, mA, o);
            mC += __shfl_xor_sync(0xffffffffu, mC, o);
        }
        if (lane == 0) { g_A[h * NSEG] = mA; g_C[h * NSEG] = mC; }
        float runA = exA, runC = exC;
#pragma unroll
        for (int pp = 0; pp < 16; pp++) {
            runA += eA[pp]; runC += eC[pp];
            int s = lane * 16 + pp + 1;
            g_A[h * NSEG + s] = mA + runA;
            g_C[h * NSEG + s] = mC + runC;
        }
    }
}

// =============================================================================
// Kernel 2: segment index per (q,k) — 4 elements per thread.
// =============================================================================
__global__ void seg_kernel(const float* __restrict__ am) {
    __shared__ float ts[RPE];
    int t = threadIdx.x;
    ts[t] = g_tsort[t];
    ts[t + 256] = g_tsort[t + 256];
    __syncthreads();
    int i0 = (blockIdx.x * 256 + t) * 4;
    float4 m4 = *(const float4*)&am[i0];
    float mv[4] = {m4.x, m4.y, m4.z, m4.w};
    unsigned short sg[4];
#pragma unroll
    for (int e = 0; e < 4; e++) {
        float m = mv[e];
        int lo = 0, hi = RPE;
        while (lo < hi) {
            int mid = (lo + hi) >> 1;
            if (ts[mid] <= m) lo = mid + 1; else hi = mid;
        }
        sg[e] = (unsigned short)lo;
    }
    *(ushort4*)&g_seg[i0] = make_ushort4(sg[0], sg[1], sg[2], sg[3]);
}

// =============================================================================
// Shared GEMM body: 64x64 tile / block, 128 threads, 4x8 per thread, BK=16.
// Inner product via fma.rn.f32x2 (W pairs packed, A duplicated).
// =============================================================================
__device__ __forceinline__ void gemm_body(const float* __restrict__ A, const float* __restrict__ W,
                                          const float* __restrict__ bias, float* __restrict__ C,
                                          int M, float scale) {
    __shared__ float As[16][68];
    __shared__ float Ws[16][72];
    int bm = blockIdx.y * 64;
    if (bm >= M) return;
    int bn = blockIdx.x * 64;
    int t = threadIdx.x;
    int ra = t >> 1, ka = (t & 1) * 8;
    int kw = t >> 3, nw = (t & 7) * 8;
    int ty = t >> 3, tx = t & 7;
    u64 acc2[4][4];
#pragma unroll
    for (int i = 0; i < 4; i++)
#pragma unroll
        for (int j = 0; j < 4; j++) acc2[i][j] = 0ull;
    for (int k0 = 0; k0 < DIMC; k0 += 16) {
        float4 a0 = *(const float4*)&A[(bm + ra) * DIMC + k0 + ka];
        float4 a1 = *(const float4*)&A[(bm + ra) * DIMC + k0 + ka + 4];
        float4 w0 = *(const float4*)&W[(k0 + kw) * DIMC + bn + nw];
        float4 w1 = *(const float4*)&W[(k0 + kw) * DIMC + bn + nw + 4];
        As[ka + 0][ra] = a0.x; As[ka + 1][ra] = a0.y; As[ka + 2][ra] = a0.z; As[ka + 3][ra] = a0.w;
        As[ka + 4][ra] = a1.x; As[ka + 5][ra] = a1.y; As[ka + 6][ra] = a1.z; As[ka + 7][ra] = a1.w;
        *(float4*)&Ws[kw][nw]     = w0;
        *(float4*)&Ws[kw][nw + 4] = w1;
        __syncthreads();
#pragma unroll
        for (int kk = 0; kk < 16; kk++) {
            float4 a4 = *(const float4*)&As[kk][ty * 4];
            ulonglong2 wp0 = *(const ulonglong2*)&Ws[kk][tx * 8];
            ulonglong2 wp1 = *(const ulonglong2*)&Ws[kk][tx * 8 + 4];
            u64 wp[4] = {wp0.x, wp0.y, wp1.x, wp1.y};
            u64 ad[4] = {pk2(a4.x, a4.x), pk2(a4.y, a4.y), pk2(a4.z, a4.z), pk2(a4.w, a4.w)};
#pragma unroll
            for (int i = 0; i < 4; i++)
#pragma unroll
                for (int j = 0; j < 4; j++)
                    fma2(acc2[i][j], ad[i], wp[j]);
        }
        __syncthreads();
    }
    float4 bsa = *(const float4*)&bias[bn + tx * 8];
    float4 bsb = *(const float4*)&bias[bn + tx * 8 + 4];
    float bs[8] = {bsa.x, bsa.y, bsa.z, bsa.w, bsb.x, bsb.y, bsb.z, bsb.w};
#pragma unroll
    for (int i = 0; i < 4; i++) {
        int row = bm + ty * 4 + i;
        float acc[8];
#pragma unroll
        for (int j = 0; j < 4; j++) {
            float2 p = up2(acc2[i][j]);
            acc[2 * j] = p.x; acc[2 * j + 1] = p.y;
        }
        float4 o0, o1;
        o0.x = (acc[0] + bs[0]) * scale; o0.y = (acc[1] + bs[1]) * scale;
        o0.z = (acc[2] + bs[2]) * scale; o0.w = (acc[3] + bs[3]) * scale;
        o1.x = (acc[4] + bs[4]) * scale; o1.y = (acc[5] + bs[5]) * scale;
        o1.z = (acc[6] + bs[6]) * scale; o1.w = (acc[7] + bs[7]) * scale;
        *(float4*)&C[row * DIMC + bn + tx * 8]     = o0;
        *(float4*)&C[row * DIMC + bn + tx * 8 + 4] = o1;
    }
}

__global__ void __launch_bounds__(128) gemm_qkv(
        const float* __restrict__ q_in, const float* __restrict__ k_in,
        const float* __restrict__ v_in,
        const float* __restrict__ Wq, const float* __restrict__ bq_,
        const float* __restrict__ Wk, const float* __restrict__ bk_,
        const float* __restrict__ Wv, const float* __restrict__ bv_) {
    const float *A, *W, *B; float *Cp; int M; float sc;
    if (blockIdx.z == 0)      { A = q_in; W = Wq; B = bq_; Cp = g_q; M = NQ; sc = 0.17677669529663687f; }
    else if (blockIdx.z == 1) { A = k_in; W = Wk; B = bk_; Cp = g_k; M = NK; sc = 1.0f; }
    else                      { A = v_in; W = Wv; B = bv_; Cp = g_v; M = NK; sc = 1.0f; }
    gemm_body(A, W, B, Cp, M, sc);
}

__global__ void __launch_bounds__(128) gemm_final(
        const float* __restrict__ Wp, const float* __restrict__ bp_,
        float* __restrict__ out) {
    gemm_body(g_x, Wp, bp_, out, NQ, 1.0f);
}

// =============================================================================
// Kernel 4: FUSED attention — 512 threads, 1 block/SM, f32x2 math.
// ST[k 1024][q 32] stride 36 (transposed scores).
// =============================================================================
#define TQ      32
#define STSTR   36
#define KTSTR   260
#define VSTR    36
#define VBUF    (128 * VSTR)
#define OFF_ST  0
#define OFF_KV  (NK * STSTR)
#define OFF_Q   (OFF_KV + 2 * VBUF)
#define OFF_AC  (OFF_Q + 32 * 36)
#define OFF_PAD (OFF_AC + 2 * NSEG + 2)
#define OFF_PM  (OFF_PAD + NK)
#define OFF_PS  (OFF_PM + 512)
#define OFF_LI  (OFF_PS + 512)
#define SMEM_FLOATS (OFF_LI + 32)
#define SMEM_BYTES  (SMEM_FLOATS * 4)

__global__ void __launch_bounds__(512, 1) fused_attn(const float* __restrict__ am,
                                                     const float* __restrict__ pad) {
    extern __shared__ float sm[];
    float*  ST   = sm + OFF_ST;
    float*  KV   = sm + OFF_KV;
    float*  Qs   = sm + OFF_Q;
    float2* AC   = (float2*)(sm + OFF_AC);
    float*  padp = sm + OFF_PAD;
    float*  pm   = sm + OFF_PM;
    float*  ps   = sm + OFF_PS;
    float*  linv = sm + OFF_LI;

    const int h    = blockIdx.y;
    const int bq   = blockIdx.x * TQ;
    const int t    = threadIdx.x;
    const int lane = t & 31, warp = t >> 5;

    // ---- prologue ----
    if (t < 256) {
        int qr = t >> 3, d4 = (t & 7) * 4;
        float4 v = *(const float4*)&g_q[(bq + qr) * DIMC + h * HD + d4];
        Qs[(d4 + 0) * 36 + qr] = v.x; Qs[(d4 + 1) * 36 + qr] = v.y;
        Qs[(d4 + 2) * 36 + qr] = v.z; Qs[(d4 + 3) * 36 + qr] = v.w;
        float4 p4 = *(const float4*)&pad[t * 4];
        float4 o; o.x = p4.x * -100.f; o.y = p4.y * -100.f; o.z = p4.z * -100.f; o.w = p4.w * -100.f;
        *(float4*)&padp[t * 4] = o;
    }
    for (int i = t; i < NSEG; i += 512)
        AC[i] = make_float2(g_A[h * NSEG + i], g_C[h * NSEG + i]);

    // ---- Phase A: 4 chunks of 256 k; thread tile 4k x 4q (q packed in pairs) ----
    const int kr   = t >> 1;
    const int half = (t & 1) * 16;
    const int tk4  = t >> 3;              // 0..63
    const int tq4  = t & 7;               // 0..7
    float* Kt = KV;

    float4 kv0, kv1, kv2, kv3;
    {
        const float* p = &g_k[kr * DIMC + h * HD + half];
        kv0 = *(const float4*)p;       kv1 = *(const float4*)(p + 4);
        kv2 = *(const float4*)(p + 8); kv3 = *(const float4*)(p + 12);
    }
    for (int c = 0; c < 4; c++) {
        __syncthreads();
        {
            float* B = Kt + half * KTSTR + kr;
            B[0 * KTSTR] = kv0.x; B[1 * KTSTR] = kv0.y; B[2 * KTSTR] = kv0.z; B[3 * KTSTR] = kv0.w;
            B[4 * KTSTR] = kv1.x; B[5 * KTSTR] = kv1.y; B[6 * KTSTR] = kv1.z; B[7 * KTSTR] = kv1.w;
            B[8 * KTSTR] = kv2.x; B[9 * KTSTR] = kv2.y; B[10* KTSTR] = kv2.z; B[11* KTSTR] = kv2.w;
            B[12* KTSTR] = kv3.x; B[13* KTSTR] = kv3.y; B[14* KTSTR] = kv3.z; B[15* KTSTR] = kv3.w;
        }
        __syncthreads();
        if (c < 3) {
            const float* p = &g_k[((c + 1) * 256 + kr) * DIMC + h * HD + half];
            kv0 = *(const float4*)p;       kv1 = *(const float4*)(p + 4);
            kv2 = *(const float4*)(p + 8); kv3 = *(const float4*)(p + 12);
        }
        // prefetch bias inputs for this chunk (hidden under the d-loop)
        const int kg0 = c * 256 + tk4 * 4;
        float4  m4[4];
        ushort4 s4[4];
#pragma unroll
        for (int j = 0; j < 4; j++) {
            int qg = bq + tq4 * 4 + j;
            m4[j] = *(const float4*)&am[qg * NK + kg0];
            s4[j] = *(const ushort4*)&g_seg[qg * NK + kg0];
        }
        u64 acc2[4][2];
#pragma unroll
        for (int i = 0; i < 4; i++) { acc2[i][0] = 0ull; acc2[i][1] = 0ull; }
#pragma unroll
        for (int d = 0; d < HD; d++) {
            float4 kb = *(const float4*)&Kt[d * KTSTR + tk4 * 4];
            ulonglong2 qp = *(const ulonglong2*)&Qs[d * 36 + tq4 * 4];
            u64 kd0 = pk2(kb.x, kb.x), kd1 = pk2(kb.y, kb.y);
            u64 kd2 = pk2(kb.z, kb.z), kd3 = pk2(kb.w, kb.w);
            fma2(acc2[0][0], kd0, qp.x); fma2(acc2[0][1], kd0, qp.y);
            fma2(acc2[1][0], kd1, qp.x); fma2(acc2[1][1], kd1, qp.y);
            fma2(acc2[2][0], kd2, qp.x); fma2(acc2[2][1], kd2, qp.y);
            fma2(acc2[3][0], kd3, qp.x); fma2(acc2[3][1], kd3, qp.y);
        }
        float acc[4][4];
#pragma unroll
        for (int i = 0; i < 4; i++) {
            float2 p0 = up2(acc2[i][0]), p1 = up2(acc2[i][1]);
            acc[i][0] = p0.x; acc[i][1] = p0.y; acc[i][2] = p1.x; acc[i][3] = p1.y;
        }
#pragma unroll
        for (int j = 0; j < 4; j++) {
            float2 c0 = AC[s4[j].x], c1 = AC[s4[j].y], c2 = AC[s4[j].z], c3 = AC[s4[j].w];
            acc[0][j] += fmaf(c0.x, m4[j].x, c0.y);
            acc[1][j] += fmaf(c1.x, m4[j].y, c1.y);
            acc[2][j] += fmaf(c2.x, m4[j].z, c2.y);
            acc[3][j] += fmaf(c3.x, m4[j].w, c3.y);
        }
#pragma unroll
        for (int i = 0; i < 4; i++) {
            float pdv = padp[kg0 + i];
            float4 o;
            o.x = acc[i][0] + pdv; o.y = acc[i][1] + pdv;
            o.z = acc[i][2] + pdv; o.w = acc[i][3] + pdv;
            *(float4*)&ST[(kg0 + i) * STSTR + tq4 * 4] = o;
        }
    }
    __syncthreads();

    // ---- Phase B: softmax; warp w covers k in [w*64, w*64+64), q = lane ----
    {
        const int kb = warp * 64;
        float mx = -3.0e38f;
#pragma unroll 4
        for (int i = 0; i < 64; i++)
            mx = fmaxf(mx, ST[(kb + i) * STSTR + lane]);
        pm[warp * 32 + lane] = mx;
        __syncthreads();
        float gm = pm[lane];
#pragma unroll
        for (int j = 1; j < 16; j++) gm = fmaxf(gm, pm[j * 32 + lane]);
        float s = 0.f;
#pragma unroll 4
        for (int i = 0; i < 64; i++) {
            int idx = (kb + i) * STSTR + lane;
            float e = __expf(ST[idx] - gm);
            ST[idx] = e;
            s += e;
        }
        ps[warp * 32 + lane] = s;
        __syncthreads();
        if (warp == 0) {
            float tot = ps[lane];
#pragma unroll
            for (int j = 1; j < 16; j++) tot += ps[j * 32 + lane];
            linv[lane] = 1.0f / tot;
        }
    }
    __syncthreads();

    // ---- Phase C: O = P V; 8 chunks of 128 k, V dbl-buffered, d packed pairs ----
    const int vkr = t >> 2;
    const int vdh = (t & 3) * 8;
    float4 v0, v1;
    {
        const float* p = &g_v[vkr * DIMC + h * HD + vdh];
        v0 = *(const float4*)p; v1 = *(const float4*)(p + 4);
        float* B = KV + vkr * VSTR + vdh;
        *(float4*)B = v0; *(float4*)(B + 4) = v1;
    }
    __syncthreads();

    const int g    = t & 15;
    const int tile = t >> 4;
    const int q0   = (tile >> 2) * 4;
    const int d0   = (tile & 3) * 8;
    u64 acc2[4][4];
#pragma unroll
    for (int qi = 0; qi < 4; qi++)
#pragma unroll
        for (int j = 0; j < 4; j++) acc2[qi][j] = 0ull;
    for (int c = 0; c < 8; c++) {
        if (c < 7) {
            const float* p = &g_v[((c + 1) * 128 + vkr) * DIMC + h * HD + vdh];
            v0 = *(const float4*)p; v1 = *(const float4*)(p + 4);
        }
        const float* Vb = KV + (c & 1) * VBUF;
#pragma unroll
        for (int i = 0; i < 8; i++) {
            int kl = i * 16 + g;
            int kg = c * 128 + kl;
            float4 pA = *(const float4*)&ST[kg * STSTR + q0];
            ulonglong2 vA = *(const ulonglong2*)&Vb[kl * VSTR + d0];
            ulonglong2 vB = *(const ulonglong2*)&Vb[kl * VSTR + d0 + 4];
            u64 vp[4] = {vA.x, vA.y, vB.x, vB.y};
            u64 pd0 = pk2(pA.x, pA.x), pd1 = pk2(pA.y, pA.y);
            u64 pd2 = pk2(pA.z, pA.z), pd3 = pk2(pA.w, pA.w);
#pragma unroll
            for (int j = 0; j < 4; j++) {
                fma2(acc2[0][j], pd0, vp[j]);
                fma2(acc2[1][j], pd1, vp[j]);
                fma2(acc2[2][j], pd2, vp[j]);
                fma2(acc2[3][j], pd3, vp[j]);
            }
        }
        if (c < 7) {
            float* B = KV + ((c + 1) & 1) * VBUF + vkr * VSTR + vdh;
            *(float4*)B = v0; *(float4*)(B + 4) = v1;
        }
        __syncthreads();
    }

    // split-k reduce over g (lane bits 0..3), shuffling packed u64
#pragma unroll
    for (int o = 1; o < 16; o <<= 1)
#pragma unroll
        for (int qi = 0; qi < 4; qi++)
#pragma unroll
            for (int j = 0; j < 4; j++)
                acc2[qi][j] += 0ull, acc2[qi][j] = [&]{
                    u64 other = __shfl_xor_sync(0xffffffffu, acc2[qi][j], o);
                    float2 a = up2(acc2[qi][j]), b = up2(other);
                    return pk2(a.x + b.x, a.y + b.y);
                }();

    if (g == 0) {
#pragma unroll
        for (int qi = 0; qi < 4; qi++) {
            int q = q0 + qi;
            float inv = linv[q];
            float2 p0 = up2(acc2[qi][0]), p1 = up2(acc2[qi][1]);
            float2 p2 = up2(acc2[qi][2]), p3 = up2(acc2[qi][3]);
            float4 oA, oB;
            oA.x = p0.x * inv; oA.y = p0.y * inv; oA.z = p1.x * inv; oA.w = p1.y * inv;
            oB.x = p2.x * inv; oB.y = p2.y * inv; oB.z = p3.x * inv; oB.w = p3.y * inv;
            float* op = &g_x[(bq + q) * DIMC + h * HD + d0];
            *(float4*)op = oA; *(float4*)(op + 4) = oB;
        }
    }
}

// =============================================================================
extern "C" void kernel_launch(void* const* d_in, const int* in_sizes, int n_in,
                              void* d_out, int out_size) {
    const float* query = (const float*)d_in[0];
    const float* kin   = (const float*)d_in[1];
    const float* vin   = (const float*)d_in[2];
    const float* pad   = (const float*)d_in[3];
    const float* am    = (const float*)d_in[4];
    const float* Wq    = (const float*)d_in[5];
    const float* bq    = (const float*)d_in[6];
    const float* Wk    = (const float*)d_in[7];
    const float* bk    = (const float*)d_in[8];
    const float* Wv    = (const float*)d_in[9];
    const float* bv    = (const float*)d_in[10];
    const float* Wp    = (const float*)d_in[11];
    const float* bp    = (const float*)d_in[12];
    const float* W1    = (const float*)d_in[13];
    const float* b1    = (const float*)d_in[14];
    const float* W2    = (const float*)d_in[15];
    float* out = (float*)d_out;

    cudaFuncSetAttribute(fused_attn, cudaFuncAttributeMaxDynamicSharedMemorySize, SMEM_BYTES);

    pwl_build<<<1, 512>>>(W1, b1, W2);
    seg_kernel<<<NQ * NK / 1024, 256>>>(am);
    gemm_qkv<<<dim3(4, 16, 3), 128>>>(query, kin, vin, Wq, bq, Wk, bk, Wv, bv);
    fused_attn<<<dim3(16, 8), 512, SMEM_BYTES>>>(am, pad);
    gemm_final<<<dim3(4, 8), 128>>>(Wp, bp, out);
}

// round 7
// speedup vs baseline: 1.0577x; 1.0421x over previous
#include <cuda_runtime.h>

#define NQ   512
#define NK   1024
#define DIMC 256
#define NH   8
#define HD   32
#define RPE  512
#define NSEG (RPE + 1)
#define KSEG 512                     // k per split
#define SPLIT 2

typedef unsigned long long u64;

// ---- packed f32x2 helpers (Blackwell) ----
__device__ __forceinline__ u64 pk2(float lo, float hi) {
    u64 r; asm("mov.b64 %0, {%1, %2};" : "=l"(r) : "f"(lo), "f"(hi)); return r;
}
__device__ __forceinline__ void fma2(u64& d, u64 a, u64 b) {
    asm("fma.rn.f32x2 %0, %1, %2, %0;" : "+l"(d) : "l"(a), "l"(b));
}
__device__ __forceinline__ float2 up2(u64 d) {
    float2 f; asm("mov.b64 {%0, %1}, %2;" : "=f"(f.x), "=f"(f.y) : "l"(d)); return f;
}

// ---------------- scratch ----------------
static __device__ float          g_tsort[RPE];
static __device__ float          g_A[NH * NSEG];
static __device__ float          g_C[NH * NSEG];
static __device__ unsigned short g_seg[NQ * NK];
static __device__ float          g_q[NQ * DIMC];
static __device__ float          g_k[NK * DIMC];
static __device__ float          g_v[NK * DIMC];
static __device__ float          g_pO[SPLIT * NQ * DIMC];   // unnormalized partial O
static __device__ float          g_pm[SPLIT * NH * NQ];     // partial max
static __device__ float          g_ps[SPLIT * NH * NQ];     // partial sum

// =============================================================================
// Kernel 1: PWL CPB bias tables (rank-sort).
// =============================================================================
__global__ void pwl_build(const float* __restrict__ W1, const float* __restrict__ b1,
                          const float* __restrict__ W2) {
    __shared__ float key[RPE];
    __shared__ float skey[RPE];
    __shared__ int   sidx[RPE];
    __shared__ float sW1[RPE], sb1[RPE];
    __shared__ float sW2[RPE * NH];

    const int tid = threadIdx.x;
    float w = W1[tid], b = b1[tid];
    float t;
    if (w != 0.0f) t = -b / w;
    else t = (b > 0.0f) ? -__int_as_float(0x7f800000) : __int_as_float(0x7f800000);
    key[tid] = t;
    sW1[tid] = w;
    sb1[tid] = b;
#pragma unroll
    for (int h = 0; h < NH; h++) sW2[tid * NH + h] = W2[tid * NH + h];
    __syncthreads();

    int rank = 0;
    float ki = t;
#pragma unroll 4
    for (int j4 = 0; j4 < RPE / 4; j4++) {
        float4 kj = *(const float4*)&key[j4 * 4];
        int j = j4 * 4;
        rank += (kj.x < ki) || (kj.x == ki && (j + 0) < tid);
        rank += (kj.y < ki) || (kj.y == ki && (j + 1) < tid);
        rank += (kj.z < ki) || (kj.z == ki && (j + 2) < tid);
        rank += (kj.w < ki) || (kj.w == ki && (j + 3) < tid);
    }
    skey[rank] = ki;
    sidx[rank] = tid;
    __syncthreads();
    g_tsort[tid] = skey[tid];

    const int warp = tid >> 5, lane = tid & 31;
    if (warp < NH) {
        const int h = warp;
        float eA[16], eC[16];
        float leA = 0.f, leC = 0.f, mA = 0.f, mC = 0.f;
#pragma unroll
        for (int pp = 0; pp < 16; pp++) {
            int p = lane * 16 + pp;
            int r = sidx[p];
            float w1 = sW1[r], bb = sb1[r], w2 = sW2[r * NH + h];
            float ca, cc; bool plus;
            if (w1 > 0.f)      { plus = true;  ca = w1 * w2; cc = bb * w2; }
            else if (w1 < 0.f) { plus = false; ca = w1 * w2; cc = bb * w2; }
            else               { plus = true;  ca = 0.f;     cc = (bb > 0.f) ? bb * w2 : 0.f; }
            float ea = plus ? ca : -ca;
            float ec = plus ? cc : -cc;
            eA[pp] = ea; eC[pp] = ec;
            leA += ea; leC += ec;
            if (!plus) { mA += ca; mC += cc; }
        }
        float inA = leA, inC = leC;
#pragma unroll
        for (int o = 1; o < 32; o <<= 1) {
            float ta = __shfl_up_sync(0xffffffffu, inA, o);
            float tc = __shfl_up_sync(0xffffffffu, inC, o);
            if (lane >= o) { inA += ta; inC += tc; }
        }
        float exA = inA - leA, exC = inC - leC;
#pragma unroll
        for (int o = 16; o > 0; o >>= 1) {
            mA += __shfl_xor_sync(0xffffffffu, mA, o);
            mC += __shfl_xor_sync(0xffffffffu, mC, o);
        }
        if (lane == 0) { g_A[h * NSEG] = mA; g_C[h * NSEG] = mC; }
        float runA = exA, runC = exC;
#pragma unroll
        for (int pp = 0; pp < 16; pp++) {
            runA += eA[pp]; runC += eC[pp];
            int s = lane * 16 + pp + 1;
            g_A[h * NSEG + s] = mA + runA;
            g_C[h * NSEG + s] = mC + runC;
        }
    }
}

// =============================================================================
// Kernel 2: segment index per (q,k).
// =============================================================================
__global__ void seg_kernel(const float* __restrict__ am) {
    __shared__ float ts[RPE];
    int t = threadIdx.x;
    ts[t] = g_tsort[t];
    ts[t + 256] = g_tsort[t + 256];
    __syncthreads();
    int i0 = (blockIdx.x * 256 + t) * 4;
    float4 m4 = *(const float4*)&am[i0];
    float mv[4] = {m4.x, m4.y, m4.z, m4.w};
    unsigned short sg[4];
#pragma unroll
    for (int e = 0; e < 4; e++) {
        float m = mv[e];
        int lo = 0, hi = RPE;
        while (lo < hi) {
            int mid = (lo + hi) >> 1;
            if (ts[mid] <= m) lo = mid + 1; else hi = mid;
        }
        sg[e] = (unsigned short)lo;
    }
    *(ushort4*)&g_seg[i0] = make_ushort4(sg[0], sg[1], sg[2], sg[3]);
}

// =============================================================================
// Kernel 3: Q/K/V projections. 64x64 tiles, 128 threads, f32x2.
// =============================================================================
__device__ __forceinline__ void gemm_body(const float* __restrict__ A, const float* __restrict__ W,
                                          const float* __restrict__ bias, float* __restrict__ C,
                                          int M, float scale) {
    __shared__ float As[16][68];
    __shared__ float Ws[16][72];
    int bm = blockIdx.y * 64;
    if (bm >= M) return;
    int bn = blockIdx.x * 64;
    int t = threadIdx.x;
    int ra = t >> 1, ka = (t & 1) * 8;
    int kw = t >> 3, nw = (t & 7) * 8;
    int ty = t >> 3, tx = t & 7;
    u64 acc2[4][4];
#pragma unroll
    for (int i = 0; i < 4; i++)
#pragma unroll
        for (int j = 0; j < 4; j++) acc2[i][j] = 0ull;
    for (int k0 = 0; k0 < DIMC; k0 += 16) {
        float4 a0 = *(const float4*)&A[(bm + ra) * DIMC + k0 + ka];
        float4 a1 = *(const float4*)&A[(bm + ra) * DIMC + k0 + ka + 4];
        float4 w0 = *(const float4*)&W[(k0 + kw) * DIMC + bn + nw];
        float4 w1 = *(const float4*)&W[(k0 + kw) * DIMC + bn + nw + 4];
        As[ka + 0][ra] = a0.x; As[ka + 1][ra] = a0.y; As[ka + 2][ra] = a0.z; As[ka + 3][ra] = a0.w;
        As[ka + 4][ra] = a1.x; As[ka + 5][ra] = a1.y; As[ka + 6][ra] = a1.z; As[ka + 7][ra] = a1.w;
        *(float4*)&Ws[kw][nw]     = w0;
        *(float4*)&Ws[kw][nw + 4] = w1;
        __syncthreads();
#pragma unroll
        for (int kk = 0; kk < 16; kk++) {
            float4 a4 = *(const float4*)&As[kk][ty * 4];
            ulonglong2 wp0 = *(const ulonglong2*)&Ws[kk][tx * 8];
            ulonglong2 wp1 = *(const ulonglong2*)&Ws[kk][tx * 8 + 4];
            u64 wp[4] = {wp0.x, wp0.y, wp1.x, wp1.y};
            u64 ad[4] = {pk2(a4.x, a4.x), pk2(a4.y, a4.y), pk2(a4.z, a4.z), pk2(a4.w, a4.w)};
#pragma unroll
            for (int i = 0; i < 4; i++)
#pragma unroll
                for (int j = 0; j < 4; j++)
                    fma2(acc2[i][j], ad[i], wp[j]);
        }
        __syncthreads();
    }
    float4 bsa = *(const float4*)&bias[bn + tx * 8];
    float4 bsb = *(const float4*)&bias[bn + tx * 8 + 4];
    float bs[8] = {bsa.x, bsa.y, bsa.z, bsa.w, bsb.x, bsb.y, bsb.z, bsb.w};
#pragma unroll
    for (int i = 0; i < 4; i++) {
        int row = bm + ty * 4 + i;
        float acc[8];
#pragma unroll
        for (int j = 0; j < 4; j++) {
            float2 p = up2(acc2[i][j]);
            acc[2 * j] = p.x; acc[2 * j + 1] = p.y;
        }
        float4 o0, o1;
        o0.x = (acc[0] + bs[0]) * scale; o0.y = (acc[1] + bs[1]) * scale;
        o0.z = (acc[2] + bs[2]) * scale; o0.w = (acc[3] + bs[3]) * scale;
        o1.x = (acc[4] + bs[4]) * scale; o1.y = (acc[5] + bs[5]) * scale;
        o1.z = (acc[6] + bs[6]) * scale; o1.w = (acc[7] + bs[7]) * scale;
        *(float4*)&C[row * DIMC + bn + tx * 8]     = o0;
        *(float4*)&C[row * DIMC + bn + tx * 8 + 4] = o1;
    }
}

__global__ void __launch_bounds__(128) gemm_qkv(
        const float* __restrict__ q_in, const float* __restrict__ k_in,
        const float* __restrict__ v_in,
        const float* __restrict__ Wq, const float* __restrict__ bq_,
        const float* __restrict__ Wk, const float* __restrict__ bk_,
        const float* __restrict__ Wv, const float* __restrict__ bv_) {
    const float *A, *W, *B; float *Cp; int M; float sc;
    if (blockIdx.z == 0)      { A = q_in; W = Wq; B = bq_; Cp = g_q; M = NQ; sc = 0.17677669529663687f; }
    else if (blockIdx.z == 1) { A = k_in; W = Wk; B = bk_; Cp = g_k; M = NK; sc = 1.0f; }
    else                      { A = v_in; W = Wv; B = bv_; Cp = g_v; M = NK; sc = 1.0f; }
    gemm_body(A, W, B, Cp, M, sc);
}

// =============================================================================
// Kernel 4: FUSED attention, k-split x2.  Grid (16 qtiles, 8 heads, 2 ksplit),
// 256 threads, 2 blocks/SM (~105KB smem, 128 regs).
// Block computes S(512k x 32q) -> local softmax (unnormalized) -> partial O.
// =============================================================================
#define TQ      32
#define STSTR   36
#define KTSTR   132
#define VSTR    36
#define OFF_ST  0                                 // 512*36        = 18432
#define OFF_KV  (KSEG * STSTR)                    // union Kt/V    =  4608
#define OFF_Q   (OFF_KV + 128 * VSTR)             // 32*36         =  1152
#define OFF_AC  (OFF_Q + 32 * 36)                 // 2*513+2       =  1028
#define OFF_PAD (OFF_AC + 2 * NSEG + 2)           // 512
#define OFF_PM  (OFF_PAD + KSEG)                  // 256
#define OFF_PS  (OFF_PM + 256)                    // 256
#define SMEM_FLOATS (OFF_PS + 256)
#define SMEM_BYTES  (SMEM_FLOATS * 4)

__global__ void __launch_bounds__(256, 2) fused_attn(const float* __restrict__ am,
                                                     const float* __restrict__ pad) {
    extern __shared__ float sm[];
    float*  ST   = sm + OFF_ST;
    float*  KV   = sm + OFF_KV;
    float*  Qs   = sm + OFF_Q;
    float2* AC   = (float2*)(sm + OFF_AC);
    float*  padp = sm + OFF_PAD;
    float*  pm   = sm + OFF_PM;
    float*  ps   = sm + OFF_PS;

    const int h    = blockIdx.y;
    const int bq   = blockIdx.x * TQ;
    const int ks   = blockIdx.z;
    const int kbase = ks * KSEG;
    const int t    = threadIdx.x;
    const int lane = t & 31, warp = t >> 5;

    // ---- prologue ----
    if (t < 256) {  // all threads
        // Qs: 256 threads cover 32q x 32d (one float4 each)
        int qr = t >> 3, d4 = (t & 7) * 4;
        float4 v = *(const float4*)&g_q[(bq + qr) * DIMC + h * HD + d4];
        Qs[(d4 + 0) * 36 + qr] = v.x; Qs[(d4 + 1) * 36 + qr] = v.y;
        Qs[(d4 + 2) * 36 + qr] = v.z; Qs[(d4 + 3) * 36 + qr] = v.w;
    }
    if (t < 128) {
        float4 p4 = *(const float4*)&pad[kbase + t * 4];
        float4 o; o.x = p4.x * -100.f; o.y = p4.y * -100.f; o.z = p4.z * -100.f; o.w = p4.w * -100.f;
        *(float4*)&padp[t * 4] = o;
    }
    for (int i = t; i < NSEG; i += 256)
        AC[i] = make_float2(g_A[h * NSEG + i], g_C[h * NSEG + i]);

    // ---- Phase A: 4 chunks of 128 k; thread tile 4k x 4q ----
    const int kr   = t >> 1;              // 0..127
    const int half = (t & 1) * 16;
    const int tk4  = t >> 3;              // 0..31
    const int tq4  = t & 7;               // 0..7
    float* Kt = KV;                       // [32 d][132]

    float4 kv0, kv1, kv2, kv3;
    {
        const float* p = &g_k[(kbase + kr) * DIMC + h * HD + half];
        kv0 = *(const float4*)p;       kv1 = *(const float4*)(p + 4);
        kv2 = *(const float4*)(p + 8); kv3 = *(const float4*)(p + 12);
    }
    for (int c = 0; c < 4; c++) {
        __syncthreads();
        {
            float* B = Kt + half * KTSTR + kr;
            B[0 * KTSTR] = kv0.x; B[1 * KTSTR] = kv0.y; B[2 * KTSTR] = kv0.z; B[3 * KTSTR] = kv0.w;
            B[4 * KTSTR] = kv1.x; B[5 * KTSTR] = kv1.y; B[6 * KTSTR] = kv1.z; B[7 * KTSTR] = kv1.w;
            B[8 * KTSTR] = kv2.x; B[9 * KTSTR] = kv2.y; B[10* KTSTR] = kv2.z; B[11* KTSTR] = kv2.w;
            B[12* KTSTR] = kv3.x; B[13* KTSTR] = kv3.y; B[14* KTSTR] = kv3.z; B[15* KTSTR] = kv3.w;
        }
        __syncthreads();
        if (c < 3) {
            const float* p = &g_k[(kbase + (c + 1) * 128 + kr) * DIMC + h * HD + half];
            kv0 = *(const float4*)p;       kv1 = *(const float4*)(p + 4);
            kv2 = *(const float4*)(p + 8); kv3 = *(const float4*)(p + 12);
        }
        const int kg0 = c * 128 + tk4 * 4;          // local k
        const int gk0 = kbase + kg0;                 // global k
        float4  m4[4];
        ushort4 s4[4];
#pragma unroll
        for (int j = 0; j < 4; j++) {
            int qg = bq + tq4 * 4 + j;
            m4[j] = *(const float4*)&am[qg * NK + gk0];
            s4[j] = *(const ushort4*)&g_seg[qg * NK + gk0];
        }
        u64 acc2[4][2];
#pragma unroll
        for (int i = 0; i < 4; i++) { acc2[i][0] = 0ull; acc2[i][1] = 0ull; }
#pragma unroll
        for (int d = 0; d < HD; d++) {
            float4 kb = *(const float4*)&Kt[d * KTSTR + tk4 * 4];
            ulonglong2 qp = *(const ulonglong2*)&Qs[d * 36 + tq4 * 4];
            u64 kd0 = pk2(kb.x, kb.x), kd1 = pk2(kb.y, kb.y);
            u64 kd2 = pk2(kb.z, kb.z), kd3 = pk2(kb.w, kb.w);
            fma2(acc2[0][0], kd0, qp.x); fma2(acc2[0][1], kd0, qp.y);
            fma2(acc2[1][0], kd1, qp.x); fma2(acc2[1][1], kd1, qp.y);
            fma2(acc2[2][0], kd2, qp.x); fma2(acc2[2][1], kd2, qp.y);
            fma2(acc2[3][0], kd3, qp.x); fma2(acc2[3][1], kd3, qp.y);
        }
        float acc[4][4];
#pragma unroll
        for (int i = 0; i < 4; i++) {
            float2 p0 = up2(acc2[i][0]), p1 = up2(acc2[i][1]);
            acc[i][0] = p0.x; acc[i][1] = p0.y; acc[i][2] = p1.x; acc[i][3] = p1.y;
        }
#pragma unroll
        for (int j = 0; j < 4; j++) {
            float2 c0 = AC[s4[j].x], c1 = AC[s4[j].y], c2 = AC[s4[j].z], c3 = AC[s4[j].w];
            acc[0][j] += fmaf(c0.x, m4[j].x, c0.y);
            acc[1][j] += fmaf(c1.x, m4[j].y, c1.y);
            acc[2][j] += fmaf(c2.x, m4[j].z, c2.y);
            acc[3][j] += fmaf(c3.x, m4[j].w, c3.y);
        }
#pragma unroll
        for (int i = 0; i < 4; i++) {
            float pdv = padp[kg0 + i];
            float4 o;
            o.x = acc[i][0] + pdv; o.y = acc[i][1] + pdv;
            o.z = acc[i][2] + pdv; o.w = acc[i][3] + pdv;
            *(float4*)&ST[(kg0 + i) * STSTR + tq4 * 4] = o;
        }
    }
    __syncthreads();

    // ---- Phase B: partial softmax; warp w covers local k [w*64, w*64+64), q = lane ----
    {
        const int kb = warp * 64;
        float mx = -3.0e38f;
#pragma unroll 4
        for (int i = 0; i < 64; i++)
            mx = fmaxf(mx, ST[(kb + i) * STSTR + lane]);
        pm[warp * 32 + lane] = mx;
        __syncthreads();
        float gm = pm[lane];
#pragma unroll
        for (int j = 1; j < 8; j++) gm = fmaxf(gm, pm[j * 32 + lane]);
        float s = 0.f;
#pragma unroll 4
        for (int i = 0; i < 64; i++) {
            int idx = (kb + i) * STSTR + lane;
            float e = __expf(ST[idx] - gm);
            ST[idx] = e;
            s += e;
        }
        ps[warp * 32 + lane] = s;
        __syncthreads();
        if (warp == 0) {
            float tot = ps[lane];
#pragma unroll
            for (int j = 1; j < 8; j++) tot += ps[j * 32 + lane];
            int idx = ks * NH * NQ + h * NQ + bq + lane;
            g_pm[idx] = gm;
            g_ps[idx] = tot;
        }
    }
    __syncthreads();

    // ---- Phase C: O_part = P_unnorm @ V; 4 chunks of 128 k, single V buf + reg prefetch ----
    const int vkr = t >> 1;               // 0..127
    const int vdh = (t & 1) * 16;
    {
        const float* p = &g_v[(kbase + vkr) * DIMC + h * HD + vdh];
        kv0 = *(const float4*)p;       kv1 = *(const float4*)(p + 4);
        kv2 = *(const float4*)(p + 8); kv3 = *(const float4*)(p + 12);
        float* B = KV + vkr * VSTR + vdh;
        *(float4*)B = kv0; *(float4*)(B + 4) = kv1;
        *(float4*)(B + 8) = kv2; *(float4*)(B + 12) = kv3;
    }
    __syncthreads();

    const int g    = t & 7;               // split-k group (lane bits 0..2)
    const int tile = t >> 3;              // 0..31
    const int q0   = (tile >> 2) * 4;
    const int d0   = (tile & 3) * 8;
    u64 acc2[4][4];
#pragma unroll
    for (int qi = 0; qi < 4; qi++)
#pragma unroll
        for (int j = 0; j < 4; j++) acc2[qi][j] = 0ull;
    for (int c = 0; c < 4; c++) {
        if (c < 3) {
            const float* p = &g_v[(kbase + (c + 1) * 128 + vkr) * DIMC + h * HD + vdh];
            kv0 = *(const float4*)p;       kv1 = *(const float4*)(p + 4);
            kv2 = *(const float4*)(p + 8); kv3 = *(const float4*)(p + 12);
        }
        const float* Vb = KV;
#pragma unroll
        for (int i = 0; i < 16; i++) {
            int kl = i * 8 + g;
            int kg = c * 128 + kl;
            float4 pA = *(const float4*)&ST[kg * STSTR + q0];
            ulonglong2 vA = *(const ulonglong2*)&Vb[kl * VSTR + d0];
            ulonglong2 vB = *(const ulonglong2*)&Vb[kl * VSTR + d0 + 4];
            u64 vp[4] = {vA.x, vA.y, vB.x, vB.y};
            u64 pd0 = pk2(pA.x, pA.x), pd1 = pk2(pA.y, pA.y);
            u64 pd2 = pk2(pA.z, pA.z), pd3 = pk2(pA.w, pA.w);
#pragma unroll
            for (int j = 0; j < 4; j++) {
                fma2(acc2[0][j], pd0, vp[j]);
                fma2(acc2[1][j], pd1, vp[j]);
                fma2(acc2[2][j], pd2, vp[j]);
                fma2(acc2[3][j], pd3, vp[j]);
            }
        }
        __syncthreads();
        if (c < 3) {
            float* B = KV + vkr * VSTR + vdh;
            *(float4*)B = kv0; *(float4*)(B + 4) = kv1;
            *(float4*)(B + 8) = kv2; *(float4*)(B + 12) = kv3;
            __syncthreads();
        }
    }

    // split-k reduce over g (lane bits 0..2)
#pragma unroll
    for (int o = 1; o < 8; o <<= 1)
#pragma unroll
        for (int qi = 0; qi < 4; qi++)
#pragma unroll
            for (int j = 0; j < 4; j++) {
                u64 other = __shfl_xor_sync(0xffffffffu, acc2[qi][j], o);
                float2 a = up2(acc2[qi][j]), b = up2(other);
                acc2[qi][j] = pk2(a.x + b.x, a.y + b.y);
            }

    if (g == 0) {
#pragma unroll
        for (int qi = 0; qi < 4; qi++) {
            int q = q0 + qi;
            float2 p0 = up2(acc2[qi][0]), p1 = up2(acc2[qi][1]);
            float2 p2 = up2(acc2[qi][2]), p3 = up2(acc2[qi][3]);
            float4 oA, oB;
            oA.x = p0.x; oA.y = p0.y; oA.z = p1.x; oA.w = p1.y;
            oB.x = p2.x; oB.y = p2.y; oB.z = p3.x; oB.w = p3.y;
            float* op = &g_pO[ks * NQ * DIMC + (bq + q) * DIMC + h * HD + d0];
            *(float4*)op = oA; *(float4*)(op + 4) = oB;
        }
    }
}

// =============================================================================
// Kernel 5: output projection WITH split-combine folded into A-load.
// Tile 16m x 64n, 128 threads, thread 2x4, BK=16.  Grid (4, 32) = 128 blocks.
// =============================================================================
__global__ void __launch_bounds__(128) gemm_final(
        const float* __restrict__ Wp, const float* __restrict__ bp_,
        float* __restrict__ out) {
    __shared__ float As[16][20];
    __shared__ float Ws[16][68];
    __shared__ float cw[16 * NH * 2];
    const int bm = blockIdx.y * 16;
    const int bn = blockIdx.x * 64;
    const int t  = threadIdx.x;

    // combine weights for this block's 16 q rows x 8 heads
    {
        int q = t >> 3, hh = t & 7;
        int i1 = hh * NQ + bm + q;
        float m1 = g_pm[i1], m2 = g_pm[NH * NQ + i1];
        float s1 = g_ps[i1], s2 = g_ps[NH * NQ + i1];
        float M = fmaxf(m1, m2);
        float w1 = __expf(m1 - M), w2 = __expf(m2 - M);
        float inv = 1.0f / (w1 * s1 + w2 * s2);
        cw[(q * NH + hh) * 2]     = w1 * inv;
        cw[(q * NH + hh) * 2 + 1] = w2 * inv;
    }
    __syncthreads();

    const int ra = t >> 2, ka = (t & 3) * 4;     // A stage (t<64)
    const int kw = t >> 3, nw = (t & 7) * 8;     // W stage
    const int ty = t >> 4, tx = t & 15;          // compute: rows ty*2, cols tx*4
    u64 acc2[2][2] = {{0ull, 0ull}, {0ull, 0ull}};
    for (int k0 = 0; k0 < DIMC; k0 += 16) {
        if (t < 64) {
            int c = k0 + ka;
            int hh = c >> 5;
            float4 o1 = *(const float4*)&g_pO[(bm + ra) * DIMC + c];
            float4 o2 = *(const float4*)&g_pO[NQ * DIMC + (bm + ra) * DIMC + c];
            float w1 = cw[(ra * NH + hh) * 2], w2 = cw[(ra * NH + hh) * 2 + 1];
            As[ka + 0][ra] = w1 * o1.x + w2 * o2.x;
            As[ka + 1][ra] = w1 * o1.y + w2 * o2.y;
            As[ka + 2][ra] = w1 * o1.z + w2 * o2.z;
            As[ka + 3][ra] = w1 * o1.w + w2 * o2.w;
        }
        *(float4*)&Ws[kw][nw]     = *(const float4*)&Wp[(k0 + kw) * DIMC + bn + nw];
        *(float4*)&Ws[kw][nw + 4] = *(const float4*)&Wp[(k0 + kw) * DIMC + bn + nw + 4];
        __syncthreads();
#pragma unroll
        for (int kk = 0; kk < 16; kk++) {
            float2 a2 = *(const float2*)&As[kk][ty * 2];
            ulonglong2 wp = *(const ulonglong2*)&Ws[kk][tx * 4];
            u64 ax = pk2(a2.x, a2.x), ay = pk2(a2.y, a2.y);
            fma2(acc2[0][0], ax, wp.x); fma2(acc2[0][1], ax, wp.y);
            fma2(acc2[1][0], ay, wp.x); fma2(acc2[1][1], ay, wp.y);
        }
        __syncthreads();
    }
    float4 bb = *(const float4*)&bp_[bn + tx * 4];
#pragma unroll
    for (int i = 0; i < 2; i++) {
        float2 p0 = up2(acc2[i][0]), p1 = up2(acc2[i][1]);
        float4 o;
        o.x = p0.x + bb.x; o.y = p0.y + bb.y;
        o.z = p1.x + bb.z; o.w = p1.y + bb.w;
        *(float4*)&out[(bm + ty * 2 + i) * DIMC + bn + tx * 4] = o;
    }
}

// =============================================================================
extern "C" void kernel_launch(void* const* d_in, const int* in_sizes, int n_in,
                              void* d_out, int out_size) {
    const float* query = (const float*)d_in[0];
    const float* kin   = (const float*)d_in[1];
    const float* vin   = (const float*)d_in[2];
    const float* pad   = (const float*)d_in[3];
    const float* am    = (const float*)d_in[4];
    const float* Wq    = (const float*)d_in[5];
    const float* bq    = (const float*)d_in[6];
    const float* Wk    = (const float*)d_in[7];
    const float* bk    = (const float*)d_in[8];
    const float* Wv    = (const float*)d_in[9];
    const float* bv    = (const float*)d_in[10];
    const float* Wp    = (const float*)d_in[11];
    const float* bp    = (const float*)d_in[12];
    const float* W1    = (const float*)d_in[13];
    const float* b1    = (const float*)d_in[14];
    const float* W2    = (const float*)d_in[15];
    float* out = (float*)d_out;

    cudaFuncSetAttribute(fused_attn, cudaFuncAttributeMaxDynamicSharedMemorySize, SMEM_BYTES);

    pwl_build<<<1, 512>>>(W1, b1, W2);
    seg_kernel<<<NQ * NK / 1024, 256>>>(am);
    gemm_qkv<<<dim3(4, 16, 3), 128>>>(query, kin, vin, Wq, bq, Wk, bk, Wv, bv);
    fused_attn<<<dim3(16, 8, 2), 256, SMEM_BYTES>>>(am, pad);
    gemm_final<<<dim3(4, 32), 128>>>(Wp, bp, out);
}